// round 5
// baseline (speedup 1.0000x reference)
#include <cuda_runtime.h>
#include <cuda_fp16.h>

#define N_NODES 100000
#define N_EDGES 1000000
#define D_FEAT 64

// Scratch (allocation-free rule: __device__ globals)
__device__ __half g_hfeats[N_NODES * D_FEAT];   // 12.8 MB fp16 feature table
__device__ __half g_exh[N_EDGES];               // 2 MB per-edge ex (fp16)
__device__ float  g_sum[N_NODES];

// Grid-barrier state. g_bargen is monotonically increasing across graph
// replays (wraps at 2^32) — internal state only, output stays deterministic.
__device__ unsigned g_barcnt = 0;
__device__ unsigned g_bargen = 0;

__device__ __forceinline__ void grid_barrier() {
    __syncthreads();
    if (threadIdx.x == 0) {
        __threadfence();                                   // publish block's writes
        unsigned gen = atomicAdd(&g_bargen, 0u);           // read gen BEFORE arriving
        __threadfence();
        if (atomicAdd(&g_barcnt, 1u) == gridDim.x - 1u) {
            g_barcnt = 0;                                  // reset for next use
            __threadfence();
            atomicAdd(&g_bargen, 1u);                      // release
        } else {
            while (*(volatile unsigned*)&g_bargen == gen) { __nanosleep(64); }
        }
        __threadfence();                                   // acquire
    }
    __syncthreads();
}

__device__ __forceinline__ unsigned pack_h2(float a, float b) {
    half2 h = __floats2half2_rn(a, b);
    return *reinterpret_cast<unsigned*>(&h);
}

__device__ __forceinline__ float dot8h(float4 a, float4 b) {
    const half2* pa = reinterpret_cast<const half2*>(&a);
    const half2* pb = reinterpret_cast<const half2*>(&b);
    float acc = 0.0f;
#pragma unroll
    for (int i = 0; i < 4; i++) {
        float2 fa = __half22float2(pa[i]);
        float2 fb = __half22float2(pb[i]);
        acc = fmaf(fa.x, fb.x, acc);
        acc = fmaf(fa.y, fb.y, acc);
    }
    return acc;
}

// ---------------------------------------------------------------------------
// One persistent kernel, three phases separated by software grid barriers.
// Phase A: zero g_sum + convert feats fp32->fp16 (16 elems/thread-iter, MLP=4)
// Phase B: per-edge fp16 dot (4 lanes/edge), ex = exp(exp(-0.01|dot|)),
//          atomicAdd into g_sum. Segment-max pass skipped exactly (softmax
//          shift-invariance; e in (0.6,1] needs no stabilization). ex is
//          rounded to fp16 and the SAME rounded value feeds the sum, so
//          rounding largely cancels in the final ratio.
// Phase C: out[e] = ex[e] / sum[dst[e]]  (streaming store).
// ---------------------------------------------------------------------------
__global__ __launch_bounds__(256, 4)
void fused_kernel(const float* __restrict__ feats,
                  const int* __restrict__ src,
                  const int* __restrict__ dst,
                  float* __restrict__ out) {
    const int gsize = gridDim.x * blockDim.x;
    const int gtid  = blockIdx.x * blockDim.x + threadIdx.x;

    // ---- Phase A: zero sums + fp32->fp16 convert -------------------------
    for (int i = gtid; i < N_NODES; i += gsize) g_sum[i] = 0.0f;

    const float4* in4 = reinterpret_cast<const float4*>(feats);
    uint4* out4 = reinterpret_cast<uint4*>(g_hfeats);
    const int nchunk = (N_NODES * D_FEAT) / 16;          // 400000
    for (int i = gtid; i < nchunk; i += gsize) {
        float4 f0 = __ldcs(in4 + i * 4 + 0);
        float4 f1 = __ldcs(in4 + i * 4 + 1);
        float4 f2 = __ldcs(in4 + i * 4 + 2);
        float4 f3 = __ldcs(in4 + i * 4 + 3);
        uint4 o0, o1;
        o0.x = pack_h2(f0.x, f0.y);  o0.y = pack_h2(f0.z, f0.w);
        o0.z = pack_h2(f1.x, f1.y);  o0.w = pack_h2(f1.z, f1.w);
        o1.x = pack_h2(f2.x, f2.y);  o1.y = pack_h2(f2.z, f2.w);
        o1.z = pack_h2(f3.x, f3.y);  o1.w = pack_h2(f3.z, f3.w);
        out4[i * 2 + 0] = o0;
        out4[i * 2 + 1] = o1;
    }

    grid_barrier();

    // ---- Phase B: edge dot + segment sum ---------------------------------
    // 4 lanes per edge; 128B fp16 row covered by 4 contiguous LDG.128.
    // gsize and (N_EDGES*4) are both multiples of 32, so warps iterate
    // uniformly and quads never straddle a loop boundary.
    for (int t = gtid; t < N_EDGES * 4; t += gsize) {
        int eid = t >> 2;
        int sub = t & 3;

        int s = __ldg(src + eid);
        int d = __ldg(dst + eid);

        const float4* fs = reinterpret_cast<const float4*>(g_hfeats + (size_t)s * D_FEAT);
        const float4* fd = reinterpret_cast<const float4*>(g_hfeats + (size_t)d * D_FEAT);

        float4 a0 = fs[sub];
        float4 a1 = fs[sub + 4];
        float4 b0 = fd[sub];
        float4 b1 = fd[sub + 4];

        float acc = dot8h(a0, b0) + dot8h(a1, b1);

        acc += __shfl_down_sync(0xFFFFFFFFu, acc, 2);
        acc += __shfl_down_sync(0xFFFFFFFFu, acc, 1);

        if (sub == 0) {
            float e   = __expf(-0.01f * fabsf(acc));  // in (0.6, 1]
            float ex  = __expf(e);                    // in (1.9, 2.8)
            __half h  = __float2half_rn(ex);
            g_exh[eid] = h;
            atomicAdd(&g_sum[d], __half2float(h));
        }
    }

    grid_barrier();

    // ---- Phase C: divide --------------------------------------------------
    for (int i = gtid; i < N_EDGES; i += gsize) {
        float v = __half2float(g_exh[i]) / g_sum[__ldg(dst + i)];
        __stcs(out + i, v);
    }
}

// ---------------------------------------------------------------------------
extern "C" void kernel_launch(void* const* d_in, const int* in_sizes, int n_in,
                              void* d_out, int out_size) {
    const float* feats = (const float*)d_in[0];
    const int*   src   = (const int*)d_in[1];
    const int*   dst   = (const int*)d_in[2];
    float* out = (float*)d_out;

    // Size the grid to guaranteed-resident blocks (software grid barrier
    // requires every block to be co-resident; occupancy query is a pure
    // host-side query, legal during capture).
    int dev = 0, sms = 0, maxb = 0;
    cudaGetDevice(&dev);
    cudaDeviceGetAttribute(&sms, cudaDevAttrMultiProcessorCount, dev);
    cudaOccupancyMaxActiveBlocksPerMultiprocessor(&maxb, fused_kernel, 256, 0);
    int bpsm = maxb < 4 ? maxb : 4;
    if (bpsm < 1) bpsm = 1;
    int grid = sms * bpsm;

    fused_kernel<<<grid, 256>>>(feats, src, dst, out);
}

// round 7
// speedup vs baseline: 1.0358x; 1.0358x over previous
#include <cuda_runtime.h>
#include <cuda_fp16.h>

#define N_NODES 100000
#define N_EDGES 1000000
#define D_FEAT 64
#define CHUNK_B 256            // edges per dynamic chunk (N_EDGES % 256 = 64 -> tail is CLAMPED)

// Scratch (allocation-free rule: __device__ globals)
__device__ __half g_hfeats[N_NODES * D_FEAT];   // 12.8 MB fp16 feature table
__device__ __half g_exh[N_EDGES];               // 2 MB per-edge ex (fp16)
__device__ float  g_sum[N_NODES];
__device__ unsigned g_workB = 0;                // dynamic-chunk ticket (reset by k1)

// Grid-barrier state. g_bargen is monotonic across graph replays (internal
// state only — outputs stay deterministic).
__device__ unsigned g_barcnt = 0;
__device__ unsigned g_bargen = 0;

__device__ __forceinline__ void grid_barrier() {
    __syncthreads();
    if (threadIdx.x == 0) {
        __threadfence();
        unsigned gen = atomicAdd(&g_bargen, 0u);
        __threadfence();
        if (atomicAdd(&g_barcnt, 1u) == gridDim.x - 1u) {
            g_barcnt = 0;
            __threadfence();
            atomicAdd(&g_bargen, 1u);
        } else {
            while (*(volatile unsigned*)&g_bargen == gen) { __nanosleep(64); }
        }
        __threadfence();
    }
    __syncthreads();
}

__device__ __forceinline__ unsigned pack_h2(float a, float b) {
    half2 h = __floats2half2_rn(a, b);
    return *reinterpret_cast<unsigned*>(&h);
}

__device__ __forceinline__ float dot8h(float4 a, float4 b) {
    const half2* pa = reinterpret_cast<const half2*>(&a);
    const half2* pb = reinterpret_cast<const half2*>(&b);
    float acc = 0.0f;
#pragma unroll
    for (int i = 0; i < 4; i++) {
        float2 fa = __half22float2(pa[i]);
        float2 fb = __half22float2(pb[i]);
        acc = fmaf(fa.x, fb.x, acc);
        acc = fmaf(fa.y, fb.y, acc);
    }
    return acc;
}

// ---------------------------------------------------------------------------
// Kernel 1: fp32->fp16 convert (8 elems/thread) + zero g_sum + reset ticket.
// ---------------------------------------------------------------------------
__global__ __launch_bounds__(256)
void convert_kernel(const float* __restrict__ feats) {
    int i = blockIdx.x * blockDim.x + threadIdx.x;        // 8-elem index
    if (i == 0) g_workB = 0;
    if (i < N_NODES) g_sum[i] = 0.0f;
    if (i >= (N_NODES * D_FEAT) / 8) return;

    const float4* in = reinterpret_cast<const float4*>(feats) + i * 2;
    float4 f0 = __ldcs(in);
    float4 f1 = __ldcs(in + 1);

    uint4 packed;
    packed.x = pack_h2(f0.x, f0.y);
    packed.y = pack_h2(f0.z, f0.w);
    packed.z = pack_h2(f1.x, f1.y);
    packed.w = pack_h2(f1.z, f1.w);
    reinterpret_cast<uint4*>(g_hfeats)[i] = packed;
}

// ---------------------------------------------------------------------------
// Kernel 2 (persistent): edge phase with dynamic 256-edge chunks (tail
// clamped: duplicate compute, suppressed writes — keeps all 32 lanes active
// for the shfl reduction), one grid barrier, then the divide phase on the
// already-resident grid.
//
// Edge phase: 4 lanes/edge; 128B fp16 row covered by 4 contiguous LDG.128.
// ex = exp(exp(-0.01|dot|)). Segment-max pass skipped exactly (softmax
// shift-invariance; e in (0.6,1] needs no stabilization). ex rounded to fp16
// and the SAME rounded value feeds the atomic sum, so rounding largely
// cancels in the final ratio.
// ---------------------------------------------------------------------------
__global__ __launch_bounds__(256, 6)
void edge_div_kernel(const int* __restrict__ src,
                     const int* __restrict__ dst,
                     float* __restrict__ out) {
    __shared__ unsigned s_base;

    const int sub  = threadIdx.x & 3;
    const int quad = threadIdx.x >> 2;                     // 0..63

    // ---- Phase B: edge dot + segment sum (dynamic chunks) ----------------
    for (;;) {
        if (threadIdx.x == 0) s_base = atomicAdd(&g_workB, (unsigned)CHUNK_B);
        __syncthreads();
        unsigned base = s_base;
        __syncthreads();                                   // read-before-overwrite
        if (base >= N_EDGES) break;

#pragma unroll
        for (int it = 0; it < CHUNK_B / 64; it++) {        // 64 edges per iter
            unsigned eid  = base + it * 64 + quad;
            unsigned eidc = eid < N_EDGES ? eid : (N_EDGES - 1u);  // tail clamp

            int s = __ldg(src + eidc);
            int d = __ldg(dst + eidc);

            const float4* fs = reinterpret_cast<const float4*>(g_hfeats + (size_t)s * D_FEAT);
            const float4* fd = reinterpret_cast<const float4*>(g_hfeats + (size_t)d * D_FEAT);

            float4 a0 = fs[sub];
            float4 a1 = fs[sub + 4];
            float4 b0 = fd[sub];
            float4 b1 = fd[sub + 4];

            float acc = dot8h(a0, b0) + dot8h(a1, b1);
            acc += __shfl_down_sync(0xFFFFFFFFu, acc, 2);
            acc += __shfl_down_sync(0xFFFFFFFFu, acc, 1);

            if (sub == 0 && eid < N_EDGES) {
                float e  = __expf(-0.01f * fabsf(acc));   // in (0.6, 1]
                float ex = __expf(e);                     // in (1.9, 2.8)
                __half h = __float2half_rn(ex);
                g_exh[eid] = h;
                atomicAdd(&g_sum[d], __half2float(h));
            }
        }
    }

    grid_barrier();

    // ---- Phase C: divide (static grid-stride, ramp-free) -----------------
    const int gsize = gridDim.x * blockDim.x;
    for (int i = blockIdx.x * blockDim.x + threadIdx.x; i < N_EDGES; i += gsize) {
        float v = __half2float(g_exh[i]) / g_sum[__ldg(dst + i)];
        __stcs(out + i, v);
    }
}

// ---------------------------------------------------------------------------
extern "C" void kernel_launch(void* const* d_in, const int* in_sizes, int n_in,
                              void* d_out, int out_size) {
    const float* feats = (const float*)d_in[0];
    const int*   src   = (const int*)d_in[1];
    const int*   dst   = (const int*)d_in[2];
    float* out = (float*)d_out;

    convert_kernel<<<((N_NODES * D_FEAT / 8) + 255) / 256, 256>>>(feats);

    // Persistent grid: guaranteed-resident blocks only (grid barrier safety).
    int dev = 0, sms = 0, maxb = 0;
    cudaGetDevice(&dev);
    cudaDeviceGetAttribute(&sms, cudaDevAttrMultiProcessorCount, dev);
    cudaOccupancyMaxActiveBlocksPerMultiprocessor(&maxb, edge_div_kernel, 256, 0);
    int bpsm = maxb < 6 ? maxb : 6;
    if (bpsm < 1) bpsm = 1;
    edge_div_kernel<<<sms * bpsm, 256>>>(src, dst, out);
}

// round 8
// speedup vs baseline: 1.1520x; 1.1122x over previous
#include <cuda_runtime.h>
#include <cuda_fp16.h>

#define N_NODES 100000
#define N_EDGES 1000000
#define D_FEAT 64

// Scratch (allocation-free rule: __device__ globals)
__device__ __half g_hfeats[N_NODES * D_FEAT];   // 12.8 MB fp16 feature table
__device__ __half g_exh[N_EDGES];               // 2 MB per-edge ex (fp16)
__device__ float  g_sum[N_NODES];

__device__ __forceinline__ unsigned pack_h2(float a, float b) {
    half2 h = __floats2half2_rn(a, b);
    return *reinterpret_cast<unsigned*>(&h);
}

__device__ __forceinline__ float dot8h(float4 a, float4 b) {
    const half2* pa = reinterpret_cast<const half2*>(&a);
    const half2* pb = reinterpret_cast<const half2*>(&b);
    float acc = 0.0f;
#pragma unroll
    for (int i = 0; i < 4; i++) {
        float2 fa = __half22float2(pa[i]);
        float2 fb = __half22float2(pb[i]);
        acc = fmaf(fa.x, fb.x, acc);
        acc = fmaf(fa.y, fb.y, acc);
    }
    return acc;
}

// ---------------------------------------------------------------------------
// Kernel 1: fp32->fp16 convert, 16 elems/thread (4 indep LDG.128 -> 2 STG.128,
// MLP=4) + fold in the g_sum zeroing (replaces the memset node).
// 400k threads.
// ---------------------------------------------------------------------------
__global__ __launch_bounds__(256)
void convert_kernel(const float* __restrict__ feats) {
    int i = blockIdx.x * blockDim.x + threadIdx.x;        // 16-elem index
    if (i < N_NODES) g_sum[i] = 0.0f;
    if (i >= (N_NODES * D_FEAT) / 16) return;

    const float4* in = reinterpret_cast<const float4*>(feats) + i * 4;
    float4 f0 = __ldcs(in + 0);
    float4 f1 = __ldcs(in + 1);
    float4 f2 = __ldcs(in + 2);
    float4 f3 = __ldcs(in + 3);

    uint4 o0, o1;
    o0.x = pack_h2(f0.x, f0.y);  o0.y = pack_h2(f0.z, f0.w);
    o0.z = pack_h2(f1.x, f1.y);  o0.w = pack_h2(f1.z, f1.w);
    o1.x = pack_h2(f2.x, f2.y);  o1.y = pack_h2(f2.z, f2.w);
    o1.z = pack_h2(f3.x, f3.y);  o1.w = pack_h2(f3.z, f3.w);

    uint4* outp = reinterpret_cast<uint4*>(g_hfeats) + i * 2;
    outp[0] = o0;
    outp[1] = o1;
}

// ---------------------------------------------------------------------------
// Kernel 2: per-edge fp16 dot (fp32 FMA), ex = exp(exp(-0.01|dot|)),
//           atomicAdd into per-dst sum.  (Exactly the proven R4 shape.)
// 4 lanes/edge; 128B fp16 row covered by 4 contiguous LDG.128.
// Segment-max pass skipped exactly (softmax shift-invariance; e in (0.6,1]
// needs no stabilization). ex rounded to fp16 and the SAME rounded value
// feeds the sum, so rounding largely cancels in the final ratio.
// ---------------------------------------------------------------------------
__global__ __launch_bounds__(256)
void edge_kernel(const int* __restrict__ src,
                 const int* __restrict__ dst) {
    int tid = blockIdx.x * blockDim.x + threadIdx.x;
    int eid = tid >> 2;      // 4 lanes per edge
    int sub = tid & 3;
    if (eid >= N_EDGES) return;

    int s = __ldg(src + eid);
    int d = __ldg(dst + eid);

    const float4* fs = reinterpret_cast<const float4*>(g_hfeats + (size_t)s * D_FEAT);
    const float4* fd = reinterpret_cast<const float4*>(g_hfeats + (size_t)d * D_FEAT);

    float4 a0 = fs[sub];
    float4 a1 = fs[sub + 4];
    float4 b0 = fd[sub];
    float4 b1 = fd[sub + 4];

    float acc = dot8h(a0, b0) + dot8h(a1, b1);

    acc += __shfl_down_sync(0xFFFFFFFFu, acc, 2);
    acc += __shfl_down_sync(0xFFFFFFFFu, acc, 1);

    if (sub == 0) {
        float e  = __expf(-0.01f * fabsf(acc));   // in (0.6, 1]
        float ex = __expf(e);                     // in (1.9, 2.8)
        __half h = __float2half_rn(ex);
        g_exh[eid] = h;
        atomicAdd(&g_sum[d], __half2float(h));
    }
}

// ---------------------------------------------------------------------------
// Kernel 3: out[e] = ex[e] / sum[dst[e]], 2 edges/thread — keeps 500k threads
// of latency-hiding while doubling gather MLP and halving index/store ops.
// N_EDGES is even; all accesses naturally aligned.
// ---------------------------------------------------------------------------
__global__ __launch_bounds__(256)
void div_kernel(const int* __restrict__ dst,
                float* __restrict__ out) {
    int i = blockIdx.x * blockDim.x + threadIdx.x;        // pair index
    if (i >= N_EDGES / 2) return;

    half2 eh = reinterpret_cast<const half2*>(g_exh)[i];
    int2  d2 = reinterpret_cast<const int2*>(dst)[i];

    float s0 = g_sum[d2.x];
    float s1 = g_sum[d2.y];
    float2 ef = __half22float2(eh);

    float2 o;
    o.x = ef.x / s0;
    o.y = ef.y / s1;
    reinterpret_cast<float2*>(out)[i] = o;
}

// ---------------------------------------------------------------------------
extern "C" void kernel_launch(void* const* d_in, const int* in_sizes, int n_in,
                              void* d_out, int out_size) {
    const float* feats = (const float*)d_in[0];
    const int*   src   = (const int*)d_in[1];
    const int*   dst   = (const int*)d_in[2];
    float* out = (float*)d_out;

    convert_kernel<<<((N_NODES * D_FEAT / 16) + 255) / 256, 256>>>(feats);
    edge_kernel<<<(N_EDGES * 4 + 255) / 256, 256>>>(src, dst);
    div_kernel<<<((N_EDGES / 2) + 255) / 256, 256>>>(dst, out);
}

// round 10
// speedup vs baseline: 1.2300x; 1.0677x over previous
#include <cuda_runtime.h>
#include <cuda_fp16.h>

#define N_NODES 100000
#define N_EDGES 1000000
#define D_FEAT 64

// Scratch (allocation-free rule: __device__ globals)
__device__ __half g_hfeats[N_NODES * D_FEAT];   // 12.8 MB fp16 feature table
__device__ __half g_exh[N_EDGES];               // 2 MB per-edge ex (fp16)
__device__ float  g_sum[N_NODES];

__device__ __forceinline__ unsigned pack_h2(float a, float b) {
    half2 h = __floats2half2_rn(a, b);
    return *reinterpret_cast<unsigned*>(&h);
}

__device__ __forceinline__ float dot8h(float4 a, float4 b) {
    const half2* pa = reinterpret_cast<const half2*>(&a);
    const half2* pb = reinterpret_cast<const half2*>(&b);
    float acc = 0.0f;
#pragma unroll
    for (int i = 0; i < 4; i++) {
        float2 fa = __half22float2(pa[i]);
        float2 fb = __half22float2(pb[i]);
        acc = fmaf(fa.x, fb.x, acc);
        acc = fmaf(fa.y, fb.y, acc);
    }
    return acc;
}

// ---------------------------------------------------------------------------
// Kernel 1: fp32->fp16 convert (best-measured shape: 8 elems/thread, 800k
// threads) + zero g_sum (replaces the memset node).
// ---------------------------------------------------------------------------
__global__ __launch_bounds__(256)
void convert_kernel(const float* __restrict__ feats) {
    int i = blockIdx.x * blockDim.x + threadIdx.x;        // 8-elem index
    if (i < N_NODES) g_sum[i] = 0.0f;
    if (i >= (N_NODES * D_FEAT) / 8) return;

    const float4* in = reinterpret_cast<const float4*>(feats) + i * 2;
    float4 f0 = __ldcs(in);
    float4 f1 = __ldcs(in + 1);

    uint4 packed;
    packed.x = pack_h2(f0.x, f0.y);
    packed.y = pack_h2(f0.z, f0.w);
    packed.z = pack_h2(f1.x, f1.y);
    packed.w = pack_h2(f1.z, f1.w);
    reinterpret_cast<uint4*>(g_hfeats)[i] = packed;
}

// ---------------------------------------------------------------------------
// Kernel 2 (PDL secondary): prefetch src/dst indices BEFORE the grid
// dependency sync (overlaps the 8MB index read + launch ramp with convert's
// tail), then gather fp16 rows, dot, ex = exp(exp(-0.01|dot|)), atomicAdd.
// 4 lanes/edge; 128B fp16 row covered by 4 contiguous LDG.128.
// Segment-max pass skipped exactly (softmax shift-invariance; e in (0.6,1]).
// ex rounded to fp16; the SAME rounded value feeds the sum (rounding largely
// cancels in the final ratio).
// ---------------------------------------------------------------------------
__global__ __launch_bounds__(256)
void edge_kernel(const int* __restrict__ src,
                 const int* __restrict__ dst) {
    int tid = blockIdx.x * blockDim.x + threadIdx.x;
    int eid = tid >> 2;      // 4 lanes per edge
    int sub = tid & 3;
    if (eid >= N_EDGES) return;

    // Independent of convert's output — issue before the dependency sync.
    int s = __ldg(src + eid);
    int d = __ldg(dst + eid);

    cudaGridDependencySynchronize();   // wait for convert's writes to be visible

    const float4* fs = reinterpret_cast<const float4*>(g_hfeats + (size_t)s * D_FEAT);
    const float4* fd = reinterpret_cast<const float4*>(g_hfeats + (size_t)d * D_FEAT);

    float4 a0 = fs[sub];
    float4 a1 = fs[sub + 4];
    float4 b0 = fd[sub];
    float4 b1 = fd[sub + 4];

    float acc = dot8h(a0, b0) + dot8h(a1, b1);

    acc += __shfl_down_sync(0xFFFFFFFFu, acc, 2);
    acc += __shfl_down_sync(0xFFFFFFFFu, acc, 1);

    if (sub == 0) {
        float e  = __expf(-0.01f * fabsf(acc));   // in (0.6, 1]
        float ex = __expf(e);                     // in (1.9, 2.8)
        __half h = __float2half_rn(ex);
        g_exh[eid] = h;
        atomicAdd(&g_sum[d], __half2float(h));
    }
}

// ---------------------------------------------------------------------------
// Kernel 3 (PDL secondary): prefetch dst pair before the sync, then
// out[e] = ex[e] / sum[dst[e]], 2 edges/thread.
// ---------------------------------------------------------------------------
__global__ __launch_bounds__(256)
void div_kernel(const int* __restrict__ dst,
                float* __restrict__ out) {
    int i = blockIdx.x * blockDim.x + threadIdx.x;        // pair index
    if (i >= N_EDGES / 2) return;

    // Independent of edge's output — issue before the dependency sync.
    int2 d2 = __ldg(reinterpret_cast<const int2*>(dst) + i);

    cudaGridDependencySynchronize();   // wait for edge's g_exh / g_sum

    half2 eh = reinterpret_cast<const half2*>(g_exh)[i];
    float s0 = g_sum[d2.x];
    float s1 = g_sum[d2.y];
    float2 ef = __half22float2(eh);

    float2 o;
    o.x = ef.x / s0;
    o.y = ef.y / s1;
    reinterpret_cast<float2*>(out)[i] = o;
}

// ---------------------------------------------------------------------------
static void launch_pdl(void* func, dim3 grid, dim3 block,
                       void** args) {
    cudaLaunchConfig_t cfg = {};
    cfg.gridDim = grid;
    cfg.blockDim = block;
    cfg.dynamicSmemBytes = 0;
    cfg.stream = 0;
    cudaLaunchAttribute attr[1];
    attr[0].id = cudaLaunchAttributeProgrammaticStreamSerialization;
    attr[0].val.programmaticStreamSerializationAllowed = 1;
    cfg.attrs = attr;
    cfg.numAttrs = 1;
    cudaLaunchKernelExC(&cfg, func, args);
}

extern "C" void kernel_launch(void* const* d_in, const int* in_sizes, int n_in,
                              void* d_out, int out_size) {
    const float* feats = (const float*)d_in[0];
    const int*   src   = (const int*)d_in[1];
    const int*   dst   = (const int*)d_in[2];
    float* out = (float*)d_out;

    convert_kernel<<<((N_NODES * D_FEAT / 8) + 255) / 256, 256>>>(feats);

    {
        void* args[2] = { (void*)&src, (void*)&dst };
        launch_pdl((void*)edge_kernel,
                   dim3((N_EDGES * 4 + 255) / 256), dim3(256), args);
    }
    {
        void* args[2] = { (void*)&dst, (void*)&out };
        launch_pdl((void*)div_kernel,
                   dim3(((N_EDGES / 2) + 255) / 256), dim3(256), args);
    }
}